// round 6
// baseline (speedup 1.0000x reference)
#include <cuda_runtime.h>

// ---------------------------------------------------------------------------
// Contrast loss:
//   zp1 = proj(z_mp), zp2 = proj(z_sc)   (8->8 MLP with ELU, shared weights)
//   m[i][j] = exp( cos(zp1_i, zp2_j) / tau )
//   loss = LAM*mean(log(rowsum/ m_ii^-1 ...))  ==
//          LAM*mean(log rs) + (1-LAM)*mean(log cs) - mean(log m_ii)
// where rs_i = sum_j m[i][j] + EPS, cs_j = sum_i m[i][j] + EPS,
// and log(m_ii) = logit_ii (no exp/log needed).
//
// Strategy:
//  K1 proj:      a_i = zp1_i/|zp1_i| * (log2e/tau),  b_j = zp2_j/|zp2_j|
//                so dot(a_i,b_j) = log2(m[i][j]); pads zero rows; inits sums.
//  K2 pairwise:  single pass over all N*N pairs. CTA = 64 rows x 1 col-chunk.
//                Thread (rg,cg): 4 rows (registers) x 4 cols per step.
//                e = ex2.approx(dot8_f32x2) -> rowacc regs + shfl-reduced
//                column sums (atomicAdd). Zero-padded rows/cols contribute
//                exactly 1.0 each; cancelled exactly via sum init offsets.
//  K3 final:     one CTA: mean(log rs) / mean(log cs) / mean(diag logits).
// ---------------------------------------------------------------------------

#define TAU   0.5f
#define LAM   0.5f
#define EPS   1e-8f
#define LOG2E 1.4426950408889634f
#define LN2   0.6931471805599453f

#define MAXPAD 16384

__device__ __align__(16) float g_a[MAXPAD * 8];
__device__ __align__(16) float g_b[MAXPAD * 8];
__device__ float g_rs[MAXPAD];
__device__ float g_cs[MAXPAD];

typedef unsigned long long u64;

// packed f32x2 dot over 8 floats (4 x b64 operands), returns scalar sum
__device__ __forceinline__ float dot8(const u64* a, const u64* b) {
    u64 acc;
    asm("mul.rn.f32x2 %0, %1, %2;"     : "=l"(acc) : "l"(a[0]), "l"(b[0]));
    asm("fma.rn.f32x2 %0, %1, %2, %3;" : "=l"(acc) : "l"(a[1]), "l"(b[1]), "l"(acc));
    asm("fma.rn.f32x2 %0, %1, %2, %3;" : "=l"(acc) : "l"(a[2]), "l"(b[2]), "l"(acc));
    asm("fma.rn.f32x2 %0, %1, %2, %3;" : "=l"(acc) : "l"(a[3]), "l"(b[3]), "l"(acc));
    float lo, hi;
    asm("mov.b64 {%0, %1}, %2;" : "=f"(lo), "=f"(hi) : "l"(acc));
    return lo + hi;
}

__device__ __forceinline__ float ex2(float x) {
    float r;
    asm("ex2.approx.ftz.f32 %0, %1;" : "=f"(r) : "f"(x));
    return r;
}

// ------------------------------- K1: projection ----------------------------
__global__ void proj_kernel(const float* __restrict__ z_mp,
                            const float* __restrict__ z_sc,
                            const float* __restrict__ W1,
                            const float* __restrict__ b1,
                            const float* __restrict__ W2,
                            const float* __restrict__ b2,
                            int N, int NpadC, float rs_init, float cs_init) {
    __shared__ float w1s[64], w2s[64], b1s[8], b2s[8];
    int t = threadIdx.x;
    if (t < 64) { w1s[t] = W1[t]; w2s[t] = W2[t]; }
    if (t < 8)  { b1s[t] = b1[t]; b2s[t] = b2[t]; }
    __syncthreads();

    int idx = blockIdx.x * blockDim.x + t;
    if (idx >= 2 * NpadC) return;
    int side = (idx >= NpadC) ? 1 : 0;     // 0 = z_mp -> g_a, 1 = z_sc -> g_b
    int row  = side ? (idx - NpadC) : idx;
    float* dst = side ? g_b : g_a;

    if (!side) { g_rs[row] = rs_init; g_cs[row] = cs_init; }

    if (row >= N) {
#pragma unroll
        for (int k = 0; k < 8; k++) dst[row * 8 + k] = 0.0f;
        return;
    }

    const float* z = (side ? z_sc : z_mp) + row * 8;
    float zr[8];
#pragma unroll
    for (int d = 0; d < 8; d++) zr[d] = z[d];

    float h[8];
#pragma unroll
    for (int k = 0; k < 8; k++) {
        float s = b1s[k];
#pragma unroll
        for (int d = 0; d < 8; d++) s = fmaf(zr[d], w1s[k * 8 + d], s);
        h[k] = (s > 0.0f) ? s : (expf(s) - 1.0f);   // ELU(alpha=1)
    }
    float o[8];
    float nn = 0.0f;
#pragma unroll
    for (int j = 0; j < 8; j++) {
        float s = b2s[j];
#pragma unroll
        for (int k = 0; k < 8; k++) s = fmaf(h[k], w2s[j * 8 + k], s);
        o[j] = s;
        nn = fmaf(s, s, nn);
    }
    float scl = (side ? 1.0f : (LOG2E / TAU)) * rsqrtf(nn);
#pragma unroll
    for (int k = 0; k < 8; k++) dst[row * 8 + k] = o[k] * scl;
}

// ------------------------------- K2: pairwise ------------------------------
// grid: (nRowBlocks, NCHUNKS). CTA: 256 threads.
// rg = tid & 15 (row group, intra-warp), cg = tid >> 4 (col group).
// Thread owns rows row0..row0+3 (registers), iterates 4-col groups stride 64.
__global__ __launch_bounds__(256, 2) void pair_kernel(int nsteps) {
    const int rg = threadIdx.x & 15;
    const int cg = threadIdx.x >> 4;
    const int row0  = blockIdx.x * 64 + rg * 4;
    const int cbase = blockIdx.y * (nsteps * 64) + cg * 4;

    const ulonglong2* ga = reinterpret_cast<const ulonglong2*>(g_a);
    const ulonglong2* gb = reinterpret_cast<const ulonglong2*>(g_b);

    u64 a[4][4];
#pragma unroll
    for (int r = 0; r < 4; r++) {
        ulonglong2 p0 = ga[(row0 + r) * 2];
        ulonglong2 p1 = ga[(row0 + r) * 2 + 1];
        a[r][0] = p0.x; a[r][1] = p0.y; a[r][2] = p1.x; a[r][3] = p1.y;
    }

    float rowacc[4] = {0.f, 0.f, 0.f, 0.f};

    for (int ts = 0; ts < nsteps; ++ts) {
        const int j0 = cbase + ts * 64;
        u64 b[4][4];
#pragma unroll
        for (int c = 0; c < 4; c++) {
            ulonglong2 p0 = gb[(j0 + c) * 2];
            ulonglong2 p1 = gb[(j0 + c) * 2 + 1];
            b[c][0] = p0.x; b[c][1] = p0.y; b[c][2] = p1.x; b[c][3] = p1.y;
        }
#pragma unroll
        for (int c = 0; c < 4; c++) {
            float cacc = 0.0f;
#pragma unroll
            for (int r = 0; r < 4; r++) {
                float e = ex2(dot8(a[r], b[c]));
                rowacc[r] += e;
                cacc += e;
            }
            // reduce column partial over the 16 row-groups (intra-half-warp)
            cacc += __shfl_xor_sync(0xffffffffu, cacc, 1);
            cacc += __shfl_xor_sync(0xffffffffu, cacc, 2);
            cacc += __shfl_xor_sync(0xffffffffu, cacc, 4);
            cacc += __shfl_xor_sync(0xffffffffu, cacc, 8);
            if (rg == 0) atomicAdd(&g_cs[j0 + c], cacc);
        }
    }

    // reduce row partials over the 16 col-groups (cross-warp, once per CTA)
    __shared__ float red[64][17];
#pragma unroll
    for (int r = 0; r < 4; r++) red[rg * 4 + r][cg] = rowacc[r];
    __syncthreads();
    if (threadIdx.x < 64) {
        float s = 0.0f;
#pragma unroll
        for (int q = 0; q < 16; q++) s += red[threadIdx.x][q];
        atomicAdd(&g_rs[blockIdx.x * 64 + threadIdx.x], s);
    }
}

// ------------------------------- K3: final ---------------------------------
__global__ void final_kernel(float* __restrict__ out, int N) {
    __shared__ float sh0[256], sh1[256], sh2[256];
    const int t = threadIdx.x;
    float lr = 0.f, lc = 0.f, dd = 0.f;
    for (int i = t; i < N; i += 256) {
        lr += logf(g_rs[i]);
        lc += logf(g_cs[i]);
        const float* a = g_a + i * 8;
        const float* b = g_b + i * 8;
        float d = 0.f;
#pragma unroll
        for (int k = 0; k < 8; k++) d = fmaf(a[k], b[k], d);
        dd += d;  // log2-domain logit; natural log = d * ln2
    }
    sh0[t] = lr; sh1[t] = lc; sh2[t] = dd;
    __syncthreads();
    for (int s = 128; s > 0; s >>= 1) {
        if (t < s) { sh0[t] += sh0[t + s]; sh1[t] += sh1[t + s]; sh2[t] += sh2[t + s]; }
        __syncthreads();
    }
    if (t == 0) {
        out[0] = (LAM * sh0[0] + (1.0f - LAM) * sh1[0] - LN2 * sh2[0]) / (float)N;
    }
}

// ------------------------------- launch -------------------------------------
extern "C" void kernel_launch(void* const* d_in, const int* in_sizes, int n_in,
                              void* d_out, int out_size) {
    const float* z_mp = (const float*)d_in[0];
    const float* z_sc = (const float*)d_in[1];
    const float* W1   = (const float*)d_in[2];
    const float* b1   = (const float*)d_in[3];
    const float* W2   = (const float*)d_in[4];
    const float* b2   = (const float*)d_in[5];
    float* out = (float*)d_out;

    const int N = in_sizes[0] / 8;

    const int NCHUNKS = 4;
    const int RB = (N + 63) / 64;                          // row blocks
    const int colsPerChunk = ((N + NCHUNKS * 64 - 1) / (NCHUNKS * 64)) * 64;
    const int NpadC = NCHUNKS * colsPerChunk;              // padded columns
    const int NpadR = RB * 64;                             // padded rows
    // padded (zero) vectors contribute ex2(0)=1 per pair -> cancel exactly
    const float rs_init = EPS - (float)(NpadC - N);
    const float cs_init = EPS - (float)(NpadR - N);

    const int pthreads = 2 * NpadC;
    proj_kernel<<<(pthreads + 255) / 256, 256>>>(z_mp, z_sc, W1, b1, W2, b2,
                                                 N, NpadC, rs_init, cs_init);

    dim3 grid(RB, NCHUNKS);
    pair_kernel<<<grid, 256>>>(colsPerChunk / 64);

    final_kernel<<<1, 256>>>(out, N);
}

// round 9
// speedup vs baseline: 1.2343x; 1.2343x over previous
#include <cuda_runtime.h>
#include <cstdint>

// ---------------------------------------------------------------------------
// Contrast loss, fused:
//   a_i = zp1_i/|zp1_i| * (log2e/tau),  b_j = zp2_j/|zp2_j|
//   m[i][j] = 2^(a_i . b_j);  loss = LAM*mean(log rs) + (1-LAM)*mean(log cs)
//                                    - LN2*mean(a_i . b_i)
// Pair kernel: one pass over all N*N pairs, double-buffered cp.async b-tiles
// in SMEM, a-rows in registers, row sums in registers, column sums via
// butterfly shfl + global atomic. Zero-padded rows/cols each contribute
// 2^0 = 1, cancelled exactly in the sum initializers.
// ---------------------------------------------------------------------------

#define TAU   0.5f
#define LAM   0.5f
#define EPS   1e-8f
#define LOG2E 1.4426950408889634f
#define LN2   0.6931471805599453f

#define MAXPAD 16384
#define NCHUNKS 8

__device__ __align__(16) float g_a[MAXPAD * 8];
__device__ __align__(16) float g_b[MAXPAD * 8];
__device__ float g_rs[MAXPAD];
__device__ float g_cs[MAXPAD];

typedef unsigned long long u64;
typedef unsigned int       u32;

__device__ __forceinline__ u32 smem_u32(const void* p) {
    u32 a;
    asm("{ .reg .u64 t; cvta.to.shared.u64 t, %1; cvt.u32.u64 %0, t; }"
        : "=r"(a) : "l"(p));
    return a;
}

__device__ __forceinline__ void cp_async8(u32 saddr, const void* gaddr) {
    asm volatile("cp.async.ca.shared.global [%0], [%1], 8;"
                 :: "r"(saddr), "l"(gaddr) : "memory");
}

// packed f32x2 dot over 8 floats (4 x b64 operands), returns scalar sum
__device__ __forceinline__ float dot8(const u64* a, const u64* b) {
    u64 acc;
    asm("mul.rn.f32x2 %0, %1, %2;"     : "=l"(acc) : "l"(a[0]), "l"(b[0]));
    asm("fma.rn.f32x2 %0, %1, %2, %3;" : "=l"(acc) : "l"(a[1]), "l"(b[1]), "l"(acc));
    asm("fma.rn.f32x2 %0, %1, %2, %3;" : "=l"(acc) : "l"(a[2]), "l"(b[2]), "l"(acc));
    asm("fma.rn.f32x2 %0, %1, %2, %3;" : "=l"(acc) : "l"(a[3]), "l"(b[3]), "l"(acc));
    float lo, hi;
    asm("mov.b64 {%0, %1}, %2;" : "=f"(lo), "=f"(hi) : "l"(acc));
    return lo + hi;
}

__device__ __forceinline__ float ex2(float x) {
    float r;
    asm("ex2.approx.ftz.f32 %0, %1;" : "=f"(r) : "f"(x));
    return r;
}

// ------------------------------- K1: projection ----------------------------
__global__ void proj_kernel(const float* __restrict__ z_mp,
                            const float* __restrict__ z_sc,
                            const float* __restrict__ W1,
                            const float* __restrict__ b1,
                            const float* __restrict__ W2,
                            const float* __restrict__ b2,
                            int N, int NpadC, float rs_init, float cs_init) {
    __shared__ float w1s[64], w2s[64], b1s[8], b2s[8];
    int t = threadIdx.x;
    if (t < 64) { w1s[t] = W1[t]; w2s[t] = W2[t]; }
    if (t < 8)  { b1s[t] = b1[t]; b2s[t] = b2[t]; }
    __syncthreads();

    int idx = blockIdx.x * blockDim.x + t;
    if (idx >= 2 * NpadC) return;
    int side = (idx >= NpadC) ? 1 : 0;     // 0 = z_mp -> g_a, 1 = z_sc -> g_b
    int row  = side ? (idx - NpadC) : idx;
    float* dst = side ? g_b : g_a;

    if (!side) { g_rs[row] = rs_init; g_cs[row] = cs_init; }

    if (row >= N) {
#pragma unroll
        for (int k = 0; k < 8; k++) dst[row * 8 + k] = 0.0f;
        return;
    }

    const float* z = (side ? z_sc : z_mp) + row * 8;
    float zr[8];
#pragma unroll
    for (int d = 0; d < 8; d++) zr[d] = z[d];

    float h[8];
#pragma unroll
    for (int k = 0; k < 8; k++) {
        float s = b1s[k];
#pragma unroll
        for (int d = 0; d < 8; d++) s = fmaf(zr[d], w1s[k * 8 + d], s);
        h[k] = (s > 0.0f) ? s : (expf(s) - 1.0f);   // ELU(alpha=1)
    }
    float o[8];
    float nn = 0.0f;
#pragma unroll
    for (int j = 0; j < 8; j++) {
        float s = b2s[j];
#pragma unroll
        for (int k = 0; k < 8; k++) s = fmaf(h[k], w2s[j * 8 + k], s);
        o[j] = s;
        nn = fmaf(s, s, nn);
    }
    float scl = (side ? 1.0f : (LOG2E / TAU)) * rsqrtf(nn);
#pragma unroll
    for (int k = 0; k < 8; k++) dst[row * 8 + k] = o[k] * scl;
}

// ------------------------------- K2: pairwise ------------------------------
// grid: (nRowBlocks, NCHUNKS). CTA: 256 threads = 16 rowgroups x 16 colgroups.
// Thread owns 4 rows (registers, fixed) x 4 cols per step (from SMEM tile).
// b tiles (64 cols x 32B = 2KB) double-buffered via cp.async.
__global__ __launch_bounds__(256, 3) void pair_kernel(int nsteps) {
    __shared__ __align__(16) float bbuf[2][64 * 8];
    __shared__ float red[64][17];

    const int tid = threadIdx.x;
    const int rg = tid & 15;
    const int cg = tid >> 4;
    const int row0   = blockIdx.x * 64 + rg * 4;
    const int jbase0 = blockIdx.y * (nsteps * 64);

    const ulonglong2* ga = reinterpret_cast<const ulonglong2*>(g_a);

    u64 a[4][4];
#pragma unroll
    for (int r = 0; r < 4; r++) {
        ulonglong2 p0 = ga[(row0 + r) * 2];
        ulonglong2 p1 = ga[(row0 + r) * 2 + 1];
        a[r][0] = p0.x; a[r][1] = p0.y; a[r][2] = p1.x; a[r][3] = p1.y;
    }

    // prefetch step 0 b-tile: 2KB, 8B per thread
    const u32 sb0 = smem_u32(&bbuf[0][0]);
    const u32 sb1 = smem_u32(&bbuf[1][0]);
    cp_async8(sb0 + tid * 8, g_b + (size_t)jbase0 * 8 + tid * 2);
    asm volatile("cp.async.commit_group;" ::: "memory");

    float rowacc[4] = {0.f, 0.f, 0.f, 0.f};

    for (int ts = 0; ts < nsteps; ++ts) {
        const int buf = ts & 1;
        if (ts + 1 < nsteps) {
            u32 dst = (buf ? sb0 : sb1) + tid * 8;
            cp_async8(dst, g_b + (size_t)(jbase0 + (ts + 1) * 64) * 8 + tid * 2);
            asm volatile("cp.async.commit_group;" ::: "memory");
            asm volatile("cp.async.wait_group 1;" ::: "memory");
        } else {
            asm volatile("cp.async.wait_group 0;" ::: "memory");
        }
        __syncthreads();

        const ulonglong2* bb = reinterpret_cast<const ulonglong2*>(&bbuf[buf][0]);
        const int j0 = jbase0 + ts * 64;
#pragma unroll
        for (int c = 0; c < 4; c++) {
            const int lc = cg * 4 + c;
            u64 bv[4];
            ulonglong2 q0 = bb[lc * 2];
            ulonglong2 q1 = bb[lc * 2 + 1];
            bv[0] = q0.x; bv[1] = q0.y; bv[2] = q1.x; bv[3] = q1.y;

            float cacc = 0.0f;
#pragma unroll
            for (int r = 0; r < 4; r++) {
                float e = ex2(dot8(a[r], bv));
                rowacc[r] += e;
                cacc += e;
            }
            // reduce over the 16 rowgroups (lane bits 0-3)
            cacc += __shfl_xor_sync(0xffffffffu, cacc, 1);
            cacc += __shfl_xor_sync(0xffffffffu, cacc, 2);
            cacc += __shfl_xor_sync(0xffffffffu, cacc, 4);
            cacc += __shfl_xor_sync(0xffffffffu, cacc, 8);
            if (rg == 0) atomicAdd(&g_cs[j0 + lc], cacc);
        }
        __syncthreads();   // all reads of bbuf[buf] done before it is refilled
    }

    // reduce row partials over the 16 colgroups, once per CTA
#pragma unroll
    for (int r = 0; r < 4; r++) red[rg * 4 + r][cg] = rowacc[r];
    __syncthreads();
    if (tid < 64) {
        float s = 0.0f;
#pragma unroll
        for (int q = 0; q < 16; q++) s += red[tid][q];
        atomicAdd(&g_rs[blockIdx.x * 64 + tid], s);
    }
}

// ------------------------------- K3: final ---------------------------------
__global__ void final_kernel(float* __restrict__ out, int N) {
    __shared__ float sh0[256], sh1[256], sh2[256];
    const int t = threadIdx.x;
    float lr = 0.f, lc = 0.f, dd = 0.f;
    for (int i = t; i < N; i += 256) {
        lr += logf(g_rs[i]);
        lc += logf(g_cs[i]);
        const float* a = g_a + i * 8;
        const float* b = g_b + i * 8;
        float d = 0.f;
#pragma unroll
        for (int k = 0; k < 8; k++) d = fmaf(a[k], b[k], d);
        dd += d;  // log2-domain logit; natural log = d * LN2
    }
    sh0[t] = lr; sh1[t] = lc; sh2[t] = dd;
    __syncthreads();
    for (int s = 128; s > 0; s >>= 1) {
        if (t < s) { sh0[t] += sh0[t + s]; sh1[t] += sh1[t + s]; sh2[t] += sh2[t + s]; }
        __syncthreads();
    }
    if (t == 0) {
        out[0] = (LAM * sh0[0] + (1.0f - LAM) * sh1[0] - LN2 * sh2[0]) / (float)N;
    }
}

// ------------------------------- launch -------------------------------------
extern "C" void kernel_launch(void* const* d_in, const int* in_sizes, int n_in,
                              void* d_out, int out_size) {
    const float* z_mp = (const float*)d_in[0];
    const float* z_sc = (const float*)d_in[1];
    const float* W1   = (const float*)d_in[2];
    const float* b1   = (const float*)d_in[3];
    const float* W2   = (const float*)d_in[4];
    const float* b2   = (const float*)d_in[5];
    float* out = (float*)d_out;

    const int N = in_sizes[0] / 8;

    const int RB = (N + 63) / 64;                              // row blocks
    const int colsPerChunk = ((N + NCHUNKS * 64 - 1) / (NCHUNKS * 64)) * 64;
    const int NpadC = NCHUNKS * colsPerChunk;                  // padded columns
    const int NpadR = RB * 64;                                 // padded rows
    // padded (zero) vectors contribute 2^0 = 1 per pair -> cancel exactly
    const float rs_init = EPS - (float)(NpadC - N);
    const float cs_init = EPS - (float)(NpadR - N);

    const int pthreads = 2 * NpadC;
    proj_kernel<<<(pthreads + 255) / 256, 256>>>(z_mp, z_sc, W1, b1, W2, b2,
                                                 N, NpadC, rs_init, cs_init);

    dim3 grid(RB, NCHUNKS);
    pair_kernel<<<grid, 256>>>(colsPerChunk / 64);

    final_kernel<<<1, 256>>>(out, N);
}

// round 10
// speedup vs baseline: 1.3794x; 1.1176x over previous
#include <cuda_runtime.h>
#include <cstdint>

// ---------------------------------------------------------------------------
// Contrast loss, fused:
//   a_i = zp1_i/|zp1_i| * (log2e/tau),  b_j = zp2_j/|zp2_j|
//   m[i][j] = 2^(a_i . b_j)
//   loss = LN2 * ( LAM*sum(lg2 rs) + (1-LAM)*sum(lg2 cs) - sum(a_i.b_i) ) / N
// Pair kernel: 4-stage cp.async pipeline, ONE barrier per step, a-rows in
// registers, row sums in registers, col sums via butterfly shfl + global RED.
// Zero-padded rows/cols contribute 2^0 = 1 each, cancelled in sum inits.
// ---------------------------------------------------------------------------

#define TAU   0.5f
#define LAM   0.5f
#define EPS   1e-8f
#define LOG2E 1.4426950408889634f
#define LN2   0.6931471805599453f

#define MAXPAD 16384
#define NCHUNKS 16

__device__ __align__(16) float g_a[MAXPAD * 8];
__device__ __align__(16) float g_b[MAXPAD * 8];
__device__ float g_rs[MAXPAD];
__device__ float g_cs[MAXPAD];
__device__ float g_part[3];

typedef unsigned long long u64;
typedef unsigned int       u32;

__device__ __forceinline__ u32 smem_u32(const void* p) {
    u32 a;
    asm("{ .reg .u64 t; cvta.to.shared.u64 t, %1; cvt.u32.u64 %0, t; }"
        : "=r"(a) : "l"(p));
    return a;
}

__device__ __forceinline__ void cp_async8(u32 saddr, const void* gaddr) {
    asm volatile("cp.async.ca.shared.global [%0], [%1], 8;"
                 :: "r"(saddr), "l"(gaddr) : "memory");
}
__device__ __forceinline__ void cp_commit() {
    asm volatile("cp.async.commit_group;" ::: "memory");
}

// packed f32x2 dot over 8 floats (4 x b64 operands), returns scalar sum
__device__ __forceinline__ float dot8(const u64* a, const u64* b) {
    u64 acc;
    asm("mul.rn.f32x2 %0, %1, %2;"     : "=l"(acc) : "l"(a[0]), "l"(b[0]));
    asm("fma.rn.f32x2 %0, %1, %2, %3;" : "=l"(acc) : "l"(a[1]), "l"(b[1]), "l"(acc));
    asm("fma.rn.f32x2 %0, %1, %2, %3;" : "=l"(acc) : "l"(a[2]), "l"(b[2]), "l"(acc));
    asm("fma.rn.f32x2 %0, %1, %2, %3;" : "=l"(acc) : "l"(a[3]), "l"(b[3]), "l"(acc));
    float lo, hi;
    asm("mov.b64 {%0, %1}, %2;" : "=f"(lo), "=f"(hi) : "l"(acc));
    return lo + hi;
}

__device__ __forceinline__ float ex2(float x) {
    float r;
    asm("ex2.approx.ftz.f32 %0, %1;" : "=f"(r) : "f"(x));
    return r;
}
__device__ __forceinline__ float lg2(float x) {
    float r;
    asm("lg2.approx.f32 %0, %1;" : "=f"(r) : "f"(x));
    return r;
}

// ------------------------------- K1: projection ----------------------------
__global__ void proj_kernel(const float* __restrict__ z_mp,
                            const float* __restrict__ z_sc,
                            const float* __restrict__ W1,
                            const float* __restrict__ b1,
                            const float* __restrict__ W2,
                            const float* __restrict__ b2,
                            int N, int NpadC, float rs_init, float cs_init) {
    __shared__ float w1s[64], w2s[64], b1s[8], b2s[8];
    int t = threadIdx.x;
    if (t < 64) { w1s[t] = W1[t]; w2s[t] = W2[t]; }
    if (t < 8)  { b1s[t] = b1[t]; b2s[t] = b2[t]; }
    if (blockIdx.x == 0 && t < 3) g_part[t] = 0.0f;
    __syncthreads();

    int idx = blockIdx.x * blockDim.x + t;
    if (idx >= 2 * NpadC) return;
    int side = (idx >= NpadC) ? 1 : 0;     // 0 = z_mp -> g_a, 1 = z_sc -> g_b
    int row  = side ? (idx - NpadC) : idx;
    float* dst = side ? g_b : g_a;

    if (!side) { g_rs[row] = rs_init; g_cs[row] = cs_init; }

    if (row >= N) {
#pragma unroll
        for (int k = 0; k < 8; k++) dst[row * 8 + k] = 0.0f;
        return;
    }

    const float* z = (side ? z_sc : z_mp) + row * 8;
    float zr[8];
#pragma unroll
    for (int d = 0; d < 8; d++) zr[d] = z[d];

    float h[8];
#pragma unroll
    for (int k = 0; k < 8; k++) {
        float s = b1s[k];
#pragma unroll
        for (int d = 0; d < 8; d++) s = fmaf(zr[d], w1s[k * 8 + d], s);
        h[k] = (s > 0.0f) ? s : (ex2(s * LOG2E) - 1.0f);   // ELU(alpha=1)
    }
    float o[8];
    float nn = 0.0f;
#pragma unroll
    for (int j = 0; j < 8; j++) {
        float s = b2s[j];
#pragma unroll
        for (int k = 0; k < 8; k++) s = fmaf(h[k], w2s[j * 8 + k], s);
        o[j] = s;
        nn = fmaf(s, s, nn);
    }
    float scl = (side ? 1.0f : (LOG2E / TAU)) * rsqrtf(nn);
#pragma unroll
    for (int k = 0; k < 8; k++) dst[row * 8 + k] = o[k] * scl;
}

// ------------------------------- K2: pairwise ------------------------------
// grid: (nRowBlocks, NCHUNKS). CTA: 256 threads = 16 rowgroups x 16 colgroups.
// Thread: 4 fixed rows (regs) x 4 cols/step from SMEM. 4-stage cp.async
// pipeline with a single barrier per step (issue-after-barrier makes buffer
// overwrite safe: all threads past barrier(ts) finished reading step ts-1).
__global__ __launch_bounds__(256, 4) void pair_kernel(int nsteps) {
    __shared__ __align__(16) float bbuf[4][64 * 8];
    __shared__ float red[64][17];

    const int tid = threadIdx.x;
    const int rg = tid & 15;
    const int cg = tid >> 4;
    const int row0   = blockIdx.x * 64 + rg * 4;
    const int jbase0 = blockIdx.y * (nsteps * 64);

    const ulonglong2* ga = reinterpret_cast<const ulonglong2*>(g_a);

    u64 a[4][4];
#pragma unroll
    for (int r = 0; r < 4; r++) {
        ulonglong2 p0 = ga[(row0 + r) * 2];
        ulonglong2 p1 = ga[(row0 + r) * 2 + 1];
        a[r][0] = p0.x; a[r][1] = p0.y; a[r][2] = p1.x; a[r][3] = p1.y;
    }

    const u32 sbase = smem_u32(&bbuf[0][0]) + tid * 8;
    const float* gbp = g_b + (size_t)jbase0 * 8 + tid * 2;

    // prologue: prefetch up to 3 tiles (2KB each, 8B/thread)
    const int npre = (nsteps < 3) ? nsteps : 3;
    for (int s = 0; s < npre; ++s) {
        cp_async8(sbase + s * 2048, gbp + s * 512);
        cp_commit();
    }

    float rowacc[4] = {0.f, 0.f, 0.f, 0.f};

    for (int ts = 0; ts < nsteps; ++ts) {
        const int rem = nsteps - ts;
        if (rem >= 3)      asm volatile("cp.async.wait_group 2;" ::: "memory");
        else if (rem == 2) asm volatile("cp.async.wait_group 1;" ::: "memory");
        else               asm volatile("cp.async.wait_group 0;" ::: "memory");
        __syncthreads();
        if (ts + 3 < nsteps) {
            cp_async8(sbase + ((ts + 3) & 3) * 2048, gbp + (ts + 3) * 512);
            cp_commit();
        }

        const ulonglong2* bb =
            reinterpret_cast<const ulonglong2*>(&bbuf[ts & 3][0]);
        const int j0 = jbase0 + ts * 64;
#pragma unroll
        for (int c = 0; c < 4; c++) {
            const int lc = cg * 4 + c;
            u64 bv[4];
            ulonglong2 q0 = bb[lc * 2];
            ulonglong2 q1 = bb[lc * 2 + 1];
            bv[0] = q0.x; bv[1] = q0.y; bv[2] = q1.x; bv[3] = q1.y;

            float cacc = 0.0f;
#pragma unroll
            for (int r = 0; r < 4; r++) {
                float e = ex2(dot8(a[r], bv));
                rowacc[r] += e;
                cacc += e;
            }
            // reduce over the 16 rowgroups (lane bits 0-3)
            cacc += __shfl_xor_sync(0xffffffffu, cacc, 1);
            cacc += __shfl_xor_sync(0xffffffffu, cacc, 2);
            cacc += __shfl_xor_sync(0xffffffffu, cacc, 4);
            cacc += __shfl_xor_sync(0xffffffffu, cacc, 8);
            if (rg == 0) atomicAdd(&g_cs[j0 + lc], cacc);
        }
    }

    // reduce row partials over the 16 colgroups, once per CTA
#pragma unroll
    for (int r = 0; r < 4; r++) red[rg * 4 + r][cg] = rowacc[r];
    __syncthreads();
    if (tid < 64) {
        float s = 0.0f;
#pragma unroll
        for (int q = 0; q < 16; q++) s += red[tid][q];
        atomicAdd(&g_rs[blockIdx.x * 64 + tid], s);
    }
}

// ------------------------------- K3: partial + combine ---------------------
__global__ void partial_kernel(int N) {
    __shared__ float sh0[256], sh1[256], sh2[256];
    const int t = threadIdx.x;
    const int i = blockIdx.x * 256 + t;
    float lr = 0.f, lc = 0.f, dd = 0.f;
    if (i < N) {
        lr = lg2(g_rs[i]);
        lc = lg2(g_cs[i]);
        const float* a = g_a + i * 8;
        const float* b = g_b + i * 8;
        float d = 0.f;
#pragma unroll
        for (int k = 0; k < 8; k++) d = fmaf(a[k], b[k], d);
        dd = d;   // log2-domain diag logit
    }
    sh0[t] = lr; sh1[t] = lc; sh2[t] = dd;
    __syncthreads();
    for (int s = 128; s > 0; s >>= 1) {
        if (t < s) { sh0[t] += sh0[t + s]; sh1[t] += sh1[t + s]; sh2[t] += sh2[t + s]; }
        __syncthreads();
    }
    if (t == 0) {
        atomicAdd(&g_part[0], sh0[0]);
        atomicAdd(&g_part[1], sh1[0]);
        atomicAdd(&g_part[2], sh2[0]);
    }
}

__global__ void combine_kernel(float* __restrict__ out, int N) {
    out[0] = LN2 * (LAM * g_part[0] + (1.0f - LAM) * g_part[1] - g_part[2])
             / (float)N;
}

// ------------------------------- launch -------------------------------------
extern "C" void kernel_launch(void* const* d_in, const int* in_sizes, int n_in,
                              void* d_out, int out_size) {
    const float* z_mp = (const float*)d_in[0];
    const float* z_sc = (const float*)d_in[1];
    const float* W1   = (const float*)d_in[2];
    const float* b1   = (const float*)d_in[3];
    const float* W2   = (const float*)d_in[4];
    const float* b2   = (const float*)d_in[5];
    float* out = (float*)d_out;

    const int N = in_sizes[0] / 8;

    const int RB = (N + 63) / 64;                              // row blocks
    const int colsPerChunk = ((N + NCHUNKS * 64 - 1) / (NCHUNKS * 64)) * 64;
    const int NpadC = NCHUNKS * colsPerChunk;                  // padded columns
    const int NpadR = RB * 64;                                 // padded rows
    // padded (zero) vectors contribute 2^0 = 1 per pair -> cancel exactly
    const float rs_init = EPS - (float)(NpadC - N);
    const float cs_init = EPS - (float)(NpadR - N);

    const int pthreads = 2 * NpadC;
    proj_kernel<<<(pthreads + 255) / 256, 256>>>(z_mp, z_sc, W1, b1, W2, b2,
                                                 N, NpadC, rs_init, cs_init);

    dim3 grid(RB, NCHUNKS);
    pair_kernel<<<grid, 256>>>(colsPerChunk / 64);

    partial_kernel<<<(N + 255) / 256, 256>>>(N);
    combine_kernel<<<1, 1>>>(out, N);
}

// round 11
// speedup vs baseline: 1.4184x; 1.0282x over previous
#include <cuda_runtime.h>
#include <cstdint>

// ---------------------------------------------------------------------------
// Contrast loss, fused:
//   a_i = zp1_i/|zp1_i| * (log2e/tau),  b_j = zp2_j/|zp2_j|
//   m[i][j] = 2^(a_i . b_j)
//   loss = LN2*( LAM*sum(lg2 rs) + (1-LAM)*sum(lg2 cs) - sum(a_i.b_i) ) / N
//
// Packed-row trick: g_ap stores rows pair-interleaved {a_{2p,k}, a_{2p+1,k}},
// g_bd stores b duplicated {b_k, b_k}. One 8-deep fma.f32x2 chain then yields
// TWO complete dot products (one per half) — no lo/hi fold, and row/col
// accumulators stay packed. fma-pipe work drops 7 -> 5 inst/pair.
// Pair kernel: 4-stage cp.async pipeline, ONE barrier per step, a-rows in
// registers, packed row sums in registers, col sums via butterfly shfl +
// global atomics. Zero-padded rows/cols contribute 2^0 = 1, cancelled in the
// sum initializers. Final reduction fused via ticket (last CTA combines).
// ---------------------------------------------------------------------------

#define TAU   0.5f
#define LAM   0.5f
#define EPS   1e-8f
#define LOG2E 1.4426950408889634f
#define LN2   0.6931471805599453f

#define MAXPAD 16384
#define NCHUNKS 16

__device__ __align__(16) float g_ap[MAXPAD * 8];    // row-pair interleaved
__device__ __align__(16) float g_bd[MAXPAD * 16];   // duplicated
__device__ float g_rs[MAXPAD];
__device__ float g_cs[MAXPAD];
__device__ float g_part[3];
__device__ unsigned int g_cnt;

typedef unsigned long long u64;
typedef unsigned int       u32;

__device__ __forceinline__ u32 smem_u32(const void* p) {
    u32 a;
    asm("{ .reg .u64 t; cvta.to.shared.u64 t, %1; cvt.u32.u64 %0, t; }"
        : "=r"(a) : "l"(p));
    return a;
}

__device__ __forceinline__ void cp_async16(u32 saddr, const void* gaddr) {
    asm volatile("cp.async.ca.shared.global [%0], [%1], 16;"
                 :: "r"(saddr), "l"(gaddr) : "memory");
}
__device__ __forceinline__ void cp_commit() {
    asm volatile("cp.async.commit_group;" ::: "memory");
}

__device__ __forceinline__ u64 mul2(u64 a, u64 b) {
    u64 r; asm("mul.rn.f32x2 %0, %1, %2;" : "=l"(r) : "l"(a), "l"(b)); return r;
}
__device__ __forceinline__ u64 fma2(u64 a, u64 b, u64 c) {
    u64 r; asm("fma.rn.f32x2 %0, %1, %2, %3;" : "=l"(r) : "l"(a), "l"(b), "l"(c));
    return r;
}
__device__ __forceinline__ u64 add2(u64 a, u64 b) {
    u64 r; asm("add.rn.f32x2 %0, %1, %2;" : "=l"(r) : "l"(a), "l"(b)); return r;
}

__device__ __forceinline__ float ex2(float x) {
    float r;
    asm("ex2.approx.ftz.f32 %0, %1;" : "=f"(r) : "f"(x));
    return r;
}
__device__ __forceinline__ float lg2(float x) {
    float r;
    asm("lg2.approx.f32 %0, %1;" : "=f"(r) : "f"(x));
    return r;
}

// ------------------------------- K1: projection ----------------------------
__global__ void proj_kernel(const float* __restrict__ z_mp,
                            const float* __restrict__ z_sc,
                            const float* __restrict__ W1,
                            const float* __restrict__ b1,
                            const float* __restrict__ W2,
                            const float* __restrict__ b2,
                            int N, int NpadC, float rs_init, float cs_init) {
    __shared__ float w1s[64], w2s[64], b1s[8], b2s[8];
    int t = threadIdx.x;
    if (t < 64) { w1s[t] = W1[t]; w2s[t] = W2[t]; }
    if (t < 8)  { b1s[t] = b1[t]; b2s[t] = b2[t]; }
    if (blockIdx.x == 0 && t < 3) g_part[t] = 0.0f;
    if (blockIdx.x == 0 && t == 3) g_cnt = 0u;
    __syncthreads();

    int idx = blockIdx.x * blockDim.x + t;
    if (idx >= 2 * NpadC) return;
    int side = (idx >= NpadC) ? 1 : 0;     // 0 = z_mp -> g_ap, 1 = z_sc -> g_bd
    int row  = side ? (idx - NpadC) : idx;

    if (!side) { g_rs[row] = rs_init; g_cs[row] = cs_init; }

    float o[8];
    if (row >= N) {
#pragma unroll
        for (int k = 0; k < 8; k++) o[k] = 0.0f;
    } else {
        const float* z = (side ? z_sc : z_mp) + row * 8;
        float zr[8];
#pragma unroll
        for (int d = 0; d < 8; d++) zr[d] = z[d];

        float h[8];
#pragma unroll
        for (int k = 0; k < 8; k++) {
            float s = b1s[k];
#pragma unroll
            for (int d = 0; d < 8; d++) s = fmaf(zr[d], w1s[k * 8 + d], s);
            h[k] = (s > 0.0f) ? s : (ex2(s * LOG2E) - 1.0f);   // ELU(alpha=1)
        }
        float nn = 0.0f;
#pragma unroll
        for (int j = 0; j < 8; j++) {
            float s = b2s[j];
#pragma unroll
            for (int k = 0; k < 8; k++) s = fmaf(h[k], w2s[j * 8 + k], s);
            o[j] = s;
            nn = fmaf(s, s, nn);
        }
        float scl = (side ? 1.0f : (LOG2E / TAU)) * rsqrtf(nn);
#pragma unroll
        for (int k = 0; k < 8; k++) o[k] *= scl;
    }

    if (!side) {
        // row-pair interleave: g_ap[(row>>1)*16 + 2k + (row&1)]
        float* dst = g_ap + (row >> 1) * 16 + (row & 1);
#pragma unroll
        for (int k = 0; k < 8; k++) dst[2 * k] = o[k];
    } else {
        // duplicate: g_bd[row*16 + 2k + {0,1}]
        float* dst = g_bd + row * 16;
#pragma unroll
        for (int k = 0; k < 8; k++) { dst[2 * k] = o[k]; dst[2 * k + 1] = o[k]; }
    }
}

// ------------------------------- K2: pairwise ------------------------------
// grid: (nRowBlocks, NCHUNKS). CTA: 256 threads = 16 rowgroups x 16 colgroups.
// Thread: 4 fixed rows (2 packed row-pairs, regs) x 4 cols/step from SMEM.
// b tiles: 64 cols x 64B(dup) = 4KB, 4-stage cp.async, one barrier per step.
__global__ __launch_bounds__(256, 4) void pair_kernel(int nsteps) {
    __shared__ __align__(16) float bbuf[4][64 * 16];
    __shared__ float red[64][17];

    const int tid = threadIdx.x;
    const int rg = tid & 15;
    const int cg = tid >> 4;
    const int row0   = blockIdx.x * 64 + rg * 4;
    const int jbase0 = blockIdx.y * (nsteps * 64);

    // a: two packed row-pairs {a_{r0,k}, a_{r1,k}}, k=0..7 each
    const u64* gap = reinterpret_cast<const u64*>(g_ap);
    u64 a2[2][8];
#pragma unroll
    for (int rp = 0; rp < 2; rp++) {
        const u64* src = gap + (size_t)(row0 / 2 + rp) * 8;
#pragma unroll
        for (int k = 0; k < 8; k++) a2[rp][k] = src[k];
    }

    const u32 sbase = smem_u32(&bbuf[0][0]) + tid * 16;
    const float* gbp = g_bd + (size_t)jbase0 * 16 + tid * 4;

    // prologue: prefetch up to 3 tiles (4KB each, 16B/thread)
    const int npre = (nsteps < 3) ? nsteps : 3;
    for (int s = 0; s < npre; ++s) {
        cp_async16(sbase + s * 4096, gbp + s * 1024);
        cp_commit();
    }

    u64 rowacc2[2] = {0ull, 0ull};   // packed {sum_r0, sum_r1} per row-pair

    for (int ts = 0; ts < nsteps; ++ts) {
        const int rem = nsteps - ts;
        if (rem >= 3)      asm volatile("cp.async.wait_group 2;" ::: "memory");
        else if (rem == 2) asm volatile("cp.async.wait_group 1;" ::: "memory");
        else               asm volatile("cp.async.wait_group 0;" ::: "memory");
        __syncthreads();
        if (ts + 3 < nsteps) {
            cp_async16(sbase + ((ts + 3) & 3) * 4096, gbp + (ts + 3) * 1024);
            cp_commit();
        }

        const u64* bb = reinterpret_cast<const u64*>(&bbuf[ts & 3][0]);
        const int j0 = jbase0 + ts * 64;
#pragma unroll
        for (int c = 0; c < 4; c++) {
            const int lc = cg * 4 + c;
            const u64* bcol = bb + lc * 8;
            // first half of both dot chains (k = 0..3)
            u64 q0 = bcol[0], q1 = bcol[1], q2 = bcol[2], q3 = bcol[3];
            u64 d0 = mul2(a2[0][0], q0);
            u64 d1 = mul2(a2[1][0], q0);
            d0 = fma2(a2[0][1], q1, d0);  d1 = fma2(a2[1][1], q1, d1);
            d0 = fma2(a2[0][2], q2, d0);  d1 = fma2(a2[1][2], q2, d1);
            d0 = fma2(a2[0][3], q3, d0);  d1 = fma2(a2[1][3], q3, d1);
            // second half (k = 4..7), reuse q regs
            q0 = bcol[4]; q1 = bcol[5]; q2 = bcol[6]; q3 = bcol[7];
            d0 = fma2(a2[0][4], q0, d0);  d1 = fma2(a2[1][4], q0, d1);
            d0 = fma2(a2[0][5], q1, d0);  d1 = fma2(a2[1][5], q1, d1);
            d0 = fma2(a2[0][6], q2, d0);  d1 = fma2(a2[1][6], q2, d1);
            d0 = fma2(a2[0][7], q3, d0);  d1 = fma2(a2[1][7], q3, d1);

            // each half of d0/d1 is a complete dot -> exponentiate per half
            float e00, e01, e10, e11;
            asm("mov.b64 {%0, %1}, %2;" : "=f"(e00), "=f"(e01) : "l"(d0));
            asm("mov.b64 {%0, %1}, %2;" : "=f"(e10), "=f"(e11) : "l"(d1));
            e00 = ex2(e00); e01 = ex2(e01); e10 = ex2(e10); e11 = ex2(e11);
            u64 e2a, e2b;
            asm("mov.b64 %0, {%1, %2};" : "=l"(e2a) : "f"(e00), "f"(e01));
            asm("mov.b64 %0, {%1, %2};" : "=l"(e2b) : "f"(e10), "f"(e11));
            rowacc2[0] = add2(rowacc2[0], e2a);
            rowacc2[1] = add2(rowacc2[1], e2b);
            float cacc = (e00 + e01) + (e10 + e11);

            // reduce over the 16 rowgroups (lane bits 0-3)
            cacc += __shfl_xor_sync(0xffffffffu, cacc, 1);
            cacc += __shfl_xor_sync(0xffffffffu, cacc, 2);
            cacc += __shfl_xor_sync(0xffffffffu, cacc, 4);
            cacc += __shfl_xor_sync(0xffffffffu, cacc, 8);
            if (rg == 0) atomicAdd(&g_cs[j0 + lc], cacc);
        }
    }

    // unpack packed row sums -> 4 scalar rows, reduce over 16 colgroups
    float ra[4];
    asm("mov.b64 {%0, %1}, %2;" : "=f"(ra[0]), "=f"(ra[1]) : "l"(rowacc2[0]));
    asm("mov.b64 {%0, %1}, %2;" : "=f"(ra[2]), "=f"(ra[3]) : "l"(rowacc2[1]));
#pragma unroll
    for (int r = 0; r < 4; r++) red[rg * 4 + r][cg] = ra[r];
    __syncthreads();
    if (tid < 64) {
        float s = 0.0f;
#pragma unroll
        for (int q = 0; q < 16; q++) s += red[tid][q];
        atomicAdd(&g_rs[blockIdx.x * 64 + tid], s);
    }
}

// ------------------------------- K3: partial + fused combine ---------------
__global__ void partial_kernel(float* __restrict__ out, int N, int nblocks) {
    __shared__ float sh0[256], sh1[256], sh2[256];
    __shared__ bool last;
    const int t = threadIdx.x;
    const int i = blockIdx.x * 256 + t;
    float lr = 0.f, lc = 0.f, dd = 0.f;
    if (i < N) {
        lr = lg2(g_rs[i]);
        lc = lg2(g_cs[i]);
        const float* a = g_ap + (i >> 1) * 16 + (i & 1);
        const float* b = g_bd + i * 16;
        float d = 0.f;
#pragma unroll
        for (int k = 0; k < 8; k++) d = fmaf(a[2 * k], b[2 * k], d);
        dd = d;   // log2-domain diag logit
    }
    sh0[t] = lr; sh1[t] = lc; sh2[t] = dd;
    __syncthreads();
    for (int s = 128; s > 0; s >>= 1) {
        if (t < s) { sh0[t] += sh0[t + s]; sh1[t] += sh1[t + s]; sh2[t] += sh2[t + s]; }
        __syncthreads();
    }
    if (t == 0) {
        atomicAdd(&g_part[0], sh0[0]);
        atomicAdd(&g_part[1], sh1[0]);
        atomicAdd(&g_part[2], sh2[0]);
        __threadfence();
        unsigned int ticket = atomicAdd(&g_cnt, 1u);
        last = (ticket == (unsigned int)(nblocks - 1));
    }
    __syncthreads();
    if (last && t == 0) {
        float p0 = atomicAdd(&g_part[0], 0.0f);
        float p1 = atomicAdd(&g_part[1], 0.0f);
        float p2 = atomicAdd(&g_part[2], 0.0f);
        out[0] = LN2 * (LAM * p0 + (1.0f - LAM) * p1 - p2) / (float)N;
    }
}

// ------------------------------- launch -------------------------------------
extern "C" void kernel_launch(void* const* d_in, const int* in_sizes, int n_in,
                              void* d_out, int out_size) {
    const float* z_mp = (const float*)d_in[0];
    const float* z_sc = (const float*)d_in[1];
    const float* W1   = (const float*)d_in[2];
    const float* b1   = (const float*)d_in[3];
    const float* W2   = (const float*)d_in[4];
    const float* b2   = (const float*)d_in[5];
    float* out = (float*)d_out;

    const int N = in_sizes[0] / 8;

    const int RB = (N + 63) / 64;                              // row blocks
    const int colsPerChunk = ((N + NCHUNKS * 64 - 1) / (NCHUNKS * 64)) * 64;
    const int NpadC = NCHUNKS * colsPerChunk;                  // padded columns
    const int NpadR = RB * 64;                                 // padded rows
    // padded (zero) vectors contribute 2^0 = 1 per pair -> cancel exactly
    const float rs_init = EPS - (float)(NpadC - N);
    const float cs_init = EPS - (float)(NpadR - N);

    const int pthreads = 2 * NpadC;
    proj_kernel<<<(pthreads + 255) / 256, 256>>>(z_mp, z_sc, W1, b1, W2, b2,
                                                 N, NpadC, rs_init, cs_init);

    dim3 grid(RB, NCHUNKS);
    pair_kernel<<<grid, 256>>>(colsPerChunk / 64);

    const int nblocks = (N + 255) / 256;
    partial_kernel<<<nblocks, 256>>>(out, N, nblocks);
}